// round 9
// baseline (speedup 1.0000x reference)
#include <cuda_runtime.h>
#include <cuda_fp16.h>
#include <cstdint>

#define D 64
#define NODES_CAP 50000
#define EDGES_CAP 1600000
#define SCAN_BLK 1024

// ---------------- scratch (static device globals; no allocation) ----------------
__device__ int      g_counts[NODES_CAP];
__device__ int      g_roff[NODES_CAP];   // partial prefix; after fill: +bsum = final roff[n+1]
__device__ int      g_bsum[64];
__device__ int      g_scan_done;
__device__ float    g_wsum[NODES_CAP];
__device__ uint32_t g_edgep[EDGES_CAP];  // packed edge: low16 = src, high16 = fp16(w) bits
// double-buffered fp16 feature rows: layer i reads g_xh[i&1], writes g_xh[(i+1)&1]
__device__ __align__(128) __half2 g_xh[2][NODES_CAP * 32];

__device__ __forceinline__ uint32_t pack_edge(int s, float w) {
    return (uint32_t)s | ((uint32_t)__half_as_ushort(__float2half_rn(w)) << 16);
}

// ---------------- zero counters ----------------
__global__ void k_zero(int n_nodes) {
    int i = blockIdx.x * blockDim.x + threadIdx.x;
    if (i < n_nodes) g_counts[i] = 0;
    if (i == 0) g_scan_done = 0;
}

// ---------------- fused init (fp16 convert + hidden=x*t0) + degree histogram ----------------
__global__ void k_initcnt(const float* __restrict__ x, const float* __restrict__ temp,
                          const int* __restrict__ dst,
                          float* __restrict__ hidden, int nd2, int E) {
    int i = blockIdx.x * blockDim.x + threadIdx.x;
    if (i < nd2) {
        float t0 = __ldg(&temp[0]);
        float2 v = ((const float2*)x)[i];
        g_xh[0][i] = __floats2half2_rn(v.x, v.y);
        ((float2*)hidden)[i] = make_float2(v.x * t0, v.y * t0);
    }
    int e4 = i * 4;
    if (e4 + 4 <= E) {
        int4 d4 = __ldg((const int4*)&dst[e4]);
        atomicAdd(&g_counts[d4.x], 1);
        atomicAdd(&g_counts[d4.y], 1);
        atomicAdd(&g_counts[d4.z], 1);
        atomicAdd(&g_counts[d4.w], 1);
    } else {
        for (int e = e4; e < E; e++) atomicAdd(&g_counts[__ldg(&dst[e])], 1);
    }
}

// ---------------- scan1 + folded block-sum scan (last-block pattern) ----------------
__global__ void k_scan1(int N, int nb) {
    __shared__ int s[SCAN_BLK];
    __shared__ int is_last;
    int tid = threadIdx.x;
    int i = blockIdx.x * SCAN_BLK + tid;
    int v = (i < N) ? g_counts[i] : 0;
    s[tid] = v;
    __syncthreads();
    for (int off = 1; off < SCAN_BLK; off <<= 1) {
        int t = (tid >= off) ? s[tid - off] : 0;
        __syncthreads();
        s[tid] += t;
        __syncthreads();
    }
    if (i < N) g_roff[i] = s[tid] - v;          // block-local exclusive prefix
    if (tid == SCAN_BLK - 1) g_bsum[blockIdx.x] = s[tid];
    __threadfence();
    if (tid == 0) is_last = (atomicAdd(&g_scan_done, 1) == nb - 1);
    __syncthreads();
    if (is_last && tid < 32) {
        int lane = tid;
        int v0 = (lane < nb) ? g_bsum[lane] : 0;
        int v1 = (lane + 32 < nb) ? g_bsum[lane + 32] : 0;
        int s0 = v0;
        #pragma unroll
        for (int off = 1; off < 32; off <<= 1) {
            int t = __shfl_up_sync(0xffffffffu, s0, off);
            if (lane >= off) s0 += t;
        }
        int tot0 = __shfl_sync(0xffffffffu, s0, 31);
        int s1 = v1;
        #pragma unroll
        for (int off = 1; off < 32; off <<= 1) {
            int t = __shfl_up_sync(0xffffffffu, s1, off);
            if (lane >= off) s1 += t;
        }
        if (lane < nb) g_bsum[lane] = s0 - v0;                  // exclusive
        if (lane + 32 < nb) g_bsum[lane + 32] = tot0 + s1 - v1;
    }
}

// ---------------- CSR fill: bump partial roff directly, add block offset at use ----------------
// After this kernel: g_roff[n] + g_bsum[n>>10] == final_roff[n+1]
__global__ void k_fill(const int* __restrict__ src, const int* __restrict__ dst,
                       const float* __restrict__ w, int E) {
    int i = blockIdx.x * blockDim.x + threadIdx.x;
    int e4 = i * 4;
    if (e4 + 4 <= E) {
        int4   s4 = __ldg((const int4*)&src[e4]);
        int4   d4 = __ldg((const int4*)&dst[e4]);
        float4 w4 = __ldg((const float4*)&w[e4]);
        int p0 = atomicAdd(&g_roff[d4.x], 1) + g_bsum[d4.x >> 10];
        int p1 = atomicAdd(&g_roff[d4.y], 1) + g_bsum[d4.y >> 10];
        int p2 = atomicAdd(&g_roff[d4.z], 1) + g_bsum[d4.z >> 10];
        int p3 = atomicAdd(&g_roff[d4.w], 1) + g_bsum[d4.w >> 10];
        g_edgep[p0] = pack_edge(s4.x, w4.x);
        g_edgep[p1] = pack_edge(s4.y, w4.y);
        g_edgep[p2] = pack_edge(s4.z, w4.z);
        g_edgep[p3] = pack_edge(s4.w, w4.w);
    } else {
        for (int e = e4; e < E; e++) {
            int d = __ldg(&dst[e]);
            int p = atomicAdd(&g_roff[d], 1) + g_bsum[d >> 10];
            g_edgep[p] = pack_edge(__ldg(&src[e]), __ldg(&w[e]));
        }
    }
}

// ---------------- fused per-layer kernel: SpMM (into smem) + tf32 MMA + epilogue ----------------
__device__ __forceinline__ uint32_t f2tf32(float f) {
    uint32_t r;
    asm("cvt.rna.tf32.f32 %0, %1;" : "=r"(r) : "f"(f));
    return r;
}

__device__ __forceinline__ float edge_w(uint32_t ep) {
    return __half2float(__ushort_as_half((unsigned short)(ep >> 16)));
}

template <int STORE_WSUM>
__global__ void k_layer(const float* __restrict__ Wl, const float* __restrict__ bl,
                        const float* __restrict__ temp, int li, int write_xh,
                        float* __restrict__ hidden, int N) {
    __shared__ uint32_t As[64][68];   // As[node][d], tf32 bits
    __shared__ uint32_t Ws[64][68];   // Ws[o][d], tf32 bits
    int tid = threadIdx.x;
    int wid = tid >> 5, lane = tid & 31;
    int bn = blockIdx.x * 64;
    float t = __ldg(&temp[li + 1]);
    const __half2* __restrict__ xin = g_xh[li & 1];
    __half2* __restrict__ xout = g_xh[(li + 1) & 1];

    for (int idx = tid; idx < 4096; idx += 256) {
        Ws[idx >> 6][idx & 63] = f2tf32(__ldg(&Wl[idx]));   // idx == o*64+d
    }

    // ---- Phase 1: SpMM for this block's 64 nodes, results straight into As ----
    #pragma unroll 1
    for (int k = 0; k < 8; k++) {
        int nloc = wid * 8 + k;
        int node = bn + nloc;
        float2 acc0 = make_float2(0.f, 0.f);
        float2 acc1 = make_float2(0.f, 0.f);
        float ws = 0.f;
        if (node < N) {
            int beg = (node == 0) ? 0 : (__ldg(&g_roff[node - 1]) + g_bsum[(node - 1) >> 10]);
            int end = __ldg(&g_roff[node]) + g_bsum[node >> 10];
            int e = beg;
            // align to 4 for int4 edge loads
            for (; (e & 3) && e < end; e++) {
                uint32_t ep = __ldg(&g_edgep[e]);
                float wt = edge_w(ep);
                if (STORE_WSUM) ws += wt;
                float2 f = __half22float2(__ldg(&xin[(ep & 0xFFFFu) * 32 + lane]));
                acc0.x = fmaf(f.x, wt, acc0.x);
                acc0.y = fmaf(f.y, wt, acc0.y);
            }
            // main: 16 edges per iteration, 16 gathers in flight
            for (; e + 16 <= end; e += 16) {
                const int4* p = (const int4*)&g_edgep[e];
                int4 q0 = __ldg(&p[0]);
                int4 q1 = __ldg(&p[1]);
                int4 q2 = __ldg(&p[2]);
                int4 q3 = __ldg(&p[3]);
                uint32_t es[16] = {
                    (uint32_t)q0.x, (uint32_t)q0.y, (uint32_t)q0.z, (uint32_t)q0.w,
                    (uint32_t)q1.x, (uint32_t)q1.y, (uint32_t)q1.z, (uint32_t)q1.w,
                    (uint32_t)q2.x, (uint32_t)q2.y, (uint32_t)q2.z, (uint32_t)q2.w,
                    (uint32_t)q3.x, (uint32_t)q3.y, (uint32_t)q3.z, (uint32_t)q3.w };
                __half2 v[16];
                #pragma unroll
                for (int j = 0; j < 16; j++)
                    v[j] = __ldg(&xin[(es[j] & 0xFFFFu) * 32 + lane]);
                #pragma unroll
                for (int j = 0; j < 16; j++) {
                    float wt = edge_w(es[j]);
                    if (STORE_WSUM) ws += wt;
                    float2 f = __half22float2(v[j]);
                    if (j & 1) {
                        acc1.x = fmaf(f.x, wt, acc1.x);
                        acc1.y = fmaf(f.y, wt, acc1.y);
                    } else {
                        acc0.x = fmaf(f.x, wt, acc0.x);
                        acc0.y = fmaf(f.y, wt, acc0.y);
                    }
                }
            }
            // 4-edge batches
            for (; e + 4 <= end; e += 4) {
                int4 q = __ldg((const int4*)&g_edgep[e]);
                uint32_t es[4] = {(uint32_t)q.x, (uint32_t)q.y, (uint32_t)q.z, (uint32_t)q.w};
                __half2 v[4];
                #pragma unroll
                for (int j = 0; j < 4; j++)
                    v[j] = __ldg(&xin[(es[j] & 0xFFFFu) * 32 + lane]);
                #pragma unroll
                for (int j = 0; j < 4; j++) {
                    float wt = edge_w(es[j]);
                    if (STORE_WSUM) ws += wt;
                    float2 f = __half22float2(v[j]);
                    if (j & 1) {
                        acc1.x = fmaf(f.x, wt, acc1.x);
                        acc1.y = fmaf(f.y, wt, acc1.y);
                    } else {
                        acc0.x = fmaf(f.x, wt, acc0.x);
                        acc0.y = fmaf(f.y, wt, acc0.y);
                    }
                }
            }
            // tail
            for (; e < end; e++) {
                uint32_t ep = __ldg(&g_edgep[e]);
                float wt = edge_w(ep);
                if (STORE_WSUM) ws += wt;
                float2 f = __half22float2(__ldg(&xin[(ep & 0xFFFFu) * 32 + lane]));
                acc0.x = fmaf(f.x, wt, acc0.x);
                acc0.y = fmaf(f.y, wt, acc0.y);
            }
            if (STORE_WSUM && lane == 0) g_wsum[node] = ws;
        }
        As[nloc][2 * lane]     = f2tf32(acc0.x + acc1.x);
        As[nloc][2 * lane + 1] = f2tf32(acc0.y + acc1.y);
    }
    __syncthreads();

    // ---- Phase 2: tf32 MMA, m16n32 per warp ----
    int g = lane >> 2, tg = lane & 3;
    int m0 = (wid & 3) * 16;
    int n0 = (wid >> 2) * 32;

    float acc[4][4] = {};
    #pragma unroll
    for (int k0 = 0; k0 < 64; k0 += 8) {
        uint32_t a0 = As[m0 + g][k0 + tg];
        uint32_t a1 = As[m0 + g + 8][k0 + tg];
        uint32_t a2 = As[m0 + g][k0 + tg + 4];
        uint32_t a3 = As[m0 + g + 8][k0 + tg + 4];
        #pragma unroll
        for (int j = 0; j < 4; j++) {
            uint32_t b0 = Ws[n0 + j * 8 + g][k0 + tg];
            uint32_t b1 = Ws[n0 + j * 8 + g][k0 + tg + 4];
            asm volatile(
                "mma.sync.aligned.m16n8k8.row.col.f32.tf32.tf32.f32 "
                "{%0,%1,%2,%3}, {%4,%5,%6,%7}, {%8,%9}, {%0,%1,%2,%3};"
                : "+f"(acc[j][0]), "+f"(acc[j][1]), "+f"(acc[j][2]), "+f"(acc[j][3])
                : "r"(a0), "r"(a1), "r"(a2), "r"(a3), "r"(b0), "r"(b1));
        }
    }

    // epilogue: thread holds rows (m0+g, m0+g+8), cols (2tg, 2tg+1) per n8-tile
    int node0 = bn + m0 + g;
    int node1 = node0 + 8;
    float ws0 = (node0 < N) ? g_wsum[node0] : 0.f;
    float ws1 = (node1 < N) ? g_wsum[node1] : 0.f;
    #pragma unroll
    for (int j = 0; j < 4; j++) {
        int o = n0 + j * 8 + 2 * tg;
        float b0 = __ldg(&bl[o]), b1 = __ldg(&bl[o + 1]);
        if (node0 < N) {
            float r0 = fmaxf(fmaf(b0, ws0, acc[j][0]), 0.f);
            float r1 = fmaxf(fmaf(b1, ws0, acc[j][1]), 0.f);
            if (write_xh) xout[node0 * 32 + (o >> 1)] = __floats2half2_rn(r0, r1);
            float2 h = *(float2*)&hidden[node0 * 64 + o];
            h.x = fmaf(r0, t, h.x);
            h.y = fmaf(r1, t, h.y);
            *(float2*)&hidden[node0 * 64 + o] = h;
        }
        if (node1 < N) {
            float r2 = fmaxf(fmaf(b0, ws1, acc[j][2]), 0.f);
            float r3 = fmaxf(fmaf(b1, ws1, acc[j][3]), 0.f);
            if (write_xh) xout[node1 * 32 + (o >> 1)] = __floats2half2_rn(r2, r3);
            float2 h = *(float2*)&hidden[node1 * 64 + o];
            h.x = fmaf(r2, t, h.x);
            h.y = fmaf(r3, t, h.y);
            *(float2*)&hidden[node1 * 64 + o] = h;
        }
    }
}

extern "C" void kernel_launch(void* const* d_in, const int* in_sizes, int n_in,
                              void* d_out, int out_size) {
    const float* x    = (const float*)d_in[0];
    const float* w    = (const float*)d_in[1];
    const float* W    = (const float*)d_in[2];
    const float* b    = (const float*)d_in[3];
    const float* temp = (const float*)d_in[4];
    const int*   src  = (const int*)d_in[5];
    const int*   dst  = (const int*)d_in[6];
    float* hidden = (float*)d_out;

    int nd = in_sizes[0];          // N * D
    int N  = nd / D;
    int E  = in_sizes[1];
    int L  = in_sizes[3] / D;
    int nd2 = nd / 2;

    k_zero<<<(N + 255) / 256, 256>>>(N);
    int e4 = (E + 3) / 4;
    int mx = (e4 > nd2) ? e4 : nd2;
    k_initcnt<<<(mx + 255) / 256, 256>>>(x, temp, dst, hidden, nd2, E);
    int nb = (N + SCAN_BLK - 1) / SCAN_BLK;
    k_scan1<<<nb, SCAN_BLK>>>(N, nb);
    k_fill<<<(e4 + 255) / 256, 256>>>(src, dst, w, E);

    int layer_blocks = (N + 63) / 64;
    for (int i = 0; i < L; i++) {
        int write_xh = (i + 1 < L) ? 1 : 0;
        if (i == 0) k_layer<1><<<layer_blocks, 256>>>(W, b, temp, 0, write_xh, hidden, N);
        else        k_layer<0><<<layer_blocks, 256>>>(W + i * D * D, b + i * D, temp, i,
                                                      write_xh, hidden, N);
    }
}

// round 11
// speedup vs baseline: 1.1276x; 1.1276x over previous
#include <cuda_runtime.h>
#include <cuda_fp16.h>
#include <cstdint>

#define D 64
#define NODES_CAP 50000
#define EDGES_CAP 1600000
#define SCAN_BLK 1024

// ---------------- scratch (static device globals; no allocation) ----------------
__device__ int   g_counts[NODES_CAP];
__device__ int   g_roff[NODES_CAP];      // partial prefix; after fill: +bsum = final roff[n+1]
__device__ int   g_bsum[64];
__device__ int   g_scan_done;
__device__ float g_wsum[NODES_CAP];
__device__ int2  g_edge[EDGES_CAP];      // (src, float_as_int(w))
// double-buffered fp16 feature rows: layer i reads g_xh[i&1], writes g_xh[(i+1)&1]
__device__ __align__(128) __half2 g_xh[2][NODES_CAP * 32];

// ---------------- zero counters ----------------
__global__ void k_zero(int n_nodes) {
    int i = blockIdx.x * blockDim.x + threadIdx.x;
    if (i < n_nodes) g_counts[i] = 0;
    if (i == 0) g_scan_done = 0;
}

// ---------------- fused init (fp16 convert + hidden=x*t0) + degree histogram ----------------
__global__ void k_initcnt(const float* __restrict__ x, const float* __restrict__ temp,
                          const int* __restrict__ dst,
                          float* __restrict__ hidden, int nd2, int E) {
    int i = blockIdx.x * blockDim.x + threadIdx.x;
    if (i < nd2) {
        float t0 = __ldg(&temp[0]);
        float2 v = ((const float2*)x)[i];
        g_xh[0][i] = __floats2half2_rn(v.x, v.y);
        ((float2*)hidden)[i] = make_float2(v.x * t0, v.y * t0);
    }
    int e4 = i * 4;
    if (e4 + 4 <= E) {
        int4 d4 = __ldg((const int4*)&dst[e4]);
        atomicAdd(&g_counts[d4.x], 1);
        atomicAdd(&g_counts[d4.y], 1);
        atomicAdd(&g_counts[d4.z], 1);
        atomicAdd(&g_counts[d4.w], 1);
    } else {
        for (int e = e4; e < E; e++) atomicAdd(&g_counts[__ldg(&dst[e])], 1);
    }
}

// ---------------- scan1 + folded block-sum scan (last-block pattern) ----------------
__global__ void k_scan1(int N, int nb) {
    __shared__ int s[SCAN_BLK];
    __shared__ int is_last;
    int tid = threadIdx.x;
    int i = blockIdx.x * SCAN_BLK + tid;
    int v = (i < N) ? g_counts[i] : 0;
    s[tid] = v;
    __syncthreads();
    for (int off = 1; off < SCAN_BLK; off <<= 1) {
        int t = (tid >= off) ? s[tid - off] : 0;
        __syncthreads();
        s[tid] += t;
        __syncthreads();
    }
    if (i < N) g_roff[i] = s[tid] - v;          // block-local exclusive prefix
    if (tid == SCAN_BLK - 1) g_bsum[blockIdx.x] = s[tid];
    __threadfence();
    if (tid == 0) is_last = (atomicAdd(&g_scan_done, 1) == nb - 1);
    __syncthreads();
    if (is_last && tid < 32) {
        int lane = tid;
        int v0 = (lane < nb) ? g_bsum[lane] : 0;
        int v1 = (lane + 32 < nb) ? g_bsum[lane + 32] : 0;
        int s0 = v0;
        #pragma unroll
        for (int off = 1; off < 32; off <<= 1) {
            int t = __shfl_up_sync(0xffffffffu, s0, off);
            if (lane >= off) s0 += t;
        }
        int tot0 = __shfl_sync(0xffffffffu, s0, 31);
        int s1 = v1;
        #pragma unroll
        for (int off = 1; off < 32; off <<= 1) {
            int t = __shfl_up_sync(0xffffffffu, s1, off);
            if (lane >= off) s1 += t;
        }
        if (lane < nb) g_bsum[lane] = s0 - v0;                  // exclusive
        if (lane + 32 < nb) g_bsum[lane + 32] = tot0 + s1 - v1;
    }
}

// ---------------- CSR fill: bump partial roff directly, add block offset at use ----------------
// After this kernel: g_roff[n] + g_bsum[n>>10] == final_roff[n+1]
__global__ void k_fill(const int* __restrict__ src, const int* __restrict__ dst,
                       const float* __restrict__ w, int E) {
    int i = blockIdx.x * blockDim.x + threadIdx.x;
    int e4 = i * 4;
    if (e4 + 4 <= E) {
        int4   s4 = __ldg((const int4*)&src[e4]);
        int4   d4 = __ldg((const int4*)&dst[e4]);
        float4 w4 = __ldg((const float4*)&w[e4]);
        int p0 = atomicAdd(&g_roff[d4.x], 1) + g_bsum[d4.x >> 10];
        int p1 = atomicAdd(&g_roff[d4.y], 1) + g_bsum[d4.y >> 10];
        int p2 = atomicAdd(&g_roff[d4.z], 1) + g_bsum[d4.z >> 10];
        int p3 = atomicAdd(&g_roff[d4.w], 1) + g_bsum[d4.w >> 10];
        g_edge[p0] = make_int2(s4.x, __float_as_int(w4.x));
        g_edge[p1] = make_int2(s4.y, __float_as_int(w4.y));
        g_edge[p2] = make_int2(s4.z, __float_as_int(w4.z));
        g_edge[p3] = make_int2(s4.w, __float_as_int(w4.w));
    } else {
        for (int e = e4; e < E; e++) {
            int d = __ldg(&dst[e]);
            int p = atomicAdd(&g_roff[d], 1) + g_bsum[d >> 10];
            g_edge[p] = make_int2(__ldg(&src[e]), __float_as_int(__ldg(&w[e])));
        }
    }
}

// ---------------- fused per-layer kernel: SpMM (into smem) + tf32 MMA + epilogue ----------------
// Phase 1: each HALF-WARP owns one node (16 lanes x 8B = one 128B row line per gather);
// a warp walks its 8 nodes as 4 pairs -> two independent edge streams in flight.
// Warp stays converged: loop to the pair max with zero-weight padding.
__device__ __forceinline__ uint32_t f2tf32(float f) {
    uint32_t r;
    asm("cvt.rna.tf32.f32 %0, %1;" : "=r"(r) : "f"(f));
    return r;
}

template <int STORE_WSUM>
__global__ void k_layer(const float* __restrict__ Wl, const float* __restrict__ bl,
                        const float* __restrict__ temp, int li, int write_xh,
                        float* __restrict__ hidden, int N) {
    __shared__ uint32_t As[64][68];   // As[node][d], tf32 bits
    __shared__ uint32_t Ws[64][68];   // Ws[o][d], tf32 bits
    int tid = threadIdx.x;
    int wid = tid >> 5, lane = tid & 31;
    int bn = blockIdx.x * 64;
    float t = __ldg(&temp[li + 1]);
    const __half2* __restrict__ xin = g_xh[li & 1];
    __half2* __restrict__ xout = g_xh[(li + 1) & 1];

    for (int idx = tid; idx < 4096; idx += 256) {
        Ws[idx >> 6][idx & 63] = f2tf32(__ldg(&Wl[idx]));   // idx == o*64+d
    }

    int half = lane >> 4;      // which node of the pair
    int hl   = lane & 15;      // lane within half-warp; features 4*hl..4*hl+3

    // ---- Phase 1: SpMM, half-warp per node, 4 node-pairs per warp ----
    #pragma unroll 1
    for (int k = 0; k < 4; k++) {
        int nloc = wid * 8 + k * 2 + half;
        int node = bn + nloc;
        float4 acc = make_float4(0.f, 0.f, 0.f, 0.f);
        float ws = 0.f;
        int beg = 0, end = 0;
        if (node < N) {
            beg = (node == 0) ? 0 : (__ldg(&g_roff[node - 1]) + g_bsum[(node - 1) >> 10]);
            end = __ldg(&g_roff[node]) + g_bsum[node >> 10];
        }
        int cnt = end - beg;
        int mxcnt = max(cnt, __shfl_xor_sync(0xffffffffu, cnt, 16));
        int e = beg;
        for (int it = 0; it < mxcnt; it += 8, e += 8) {
            int2 ed[8];
            uint2 v[8];
            #pragma unroll
            for (int j = 0; j < 8; j++)
                ed[j] = (e + j < end) ? __ldg(&g_edge[e + j]) : make_int2(0, 0);
            #pragma unroll
            for (int j = 0; j < 8; j++)
                v[j] = __ldg((const uint2*)(xin + ed[j].x * 32) + hl);
            #pragma unroll
            for (int j = 0; j < 8; j++) {
                float wt = __int_as_float(ed[j].y);     // 0.0f for padding
                if (STORE_WSUM) ws += wt;
                float2 f0 = __half22float2(*(__half2*)&v[j].x);
                float2 f1 = __half22float2(*(__half2*)&v[j].y);
                acc.x = fmaf(f0.x, wt, acc.x);
                acc.y = fmaf(f0.y, wt, acc.y);
                acc.z = fmaf(f1.x, wt, acc.z);
                acc.w = fmaf(f1.y, wt, acc.w);
            }
        }
        if (STORE_WSUM && hl == 0 && node < N) g_wsum[node] = ws;
        As[nloc][4 * hl + 0] = f2tf32(acc.x);
        As[nloc][4 * hl + 1] = f2tf32(acc.y);
        As[nloc][4 * hl + 2] = f2tf32(acc.z);
        As[nloc][4 * hl + 3] = f2tf32(acc.w);
    }
    __syncthreads();

    // ---- Phase 2: tf32 MMA, m16n32 per warp ----
    int g = lane >> 2, tg = lane & 3;
    int m0 = (wid & 3) * 16;
    int n0 = (wid >> 2) * 32;

    float acc[4][4] = {};
    #pragma unroll
    for (int k0 = 0; k0 < 64; k0 += 8) {
        uint32_t a0 = As[m0 + g][k0 + tg];
        uint32_t a1 = As[m0 + g + 8][k0 + tg];
        uint32_t a2 = As[m0 + g][k0 + tg + 4];
        uint32_t a3 = As[m0 + g + 8][k0 + tg + 4];
        #pragma unroll
        for (int j = 0; j < 4; j++) {
            uint32_t b0 = Ws[n0 + j * 8 + g][k0 + tg];
            uint32_t b1 = Ws[n0 + j * 8 + g][k0 + tg + 4];
            asm volatile(
                "mma.sync.aligned.m16n8k8.row.col.f32.tf32.tf32.f32 "
                "{%0,%1,%2,%3}, {%4,%5,%6,%7}, {%8,%9}, {%0,%1,%2,%3};"
                : "+f"(acc[j][0]), "+f"(acc[j][1]), "+f"(acc[j][2]), "+f"(acc[j][3])
                : "r"(a0), "r"(a1), "r"(a2), "r"(a3), "r"(b0), "r"(b1));
        }
    }

    // epilogue: thread holds rows (m0+g, m0+g+8), cols (2tg, 2tg+1) per n8-tile
    int node0 = bn + m0 + g;
    int node1 = node0 + 8;
    float ws0 = (node0 < N) ? g_wsum[node0] : 0.f;
    float ws1 = (node1 < N) ? g_wsum[node1] : 0.f;
    #pragma unroll
    for (int j = 0; j < 4; j++) {
        int o = n0 + j * 8 + 2 * tg;
        float b0 = __ldg(&bl[o]), b1 = __ldg(&bl[o + 1]);
        if (node0 < N) {
            float r0 = fmaxf(fmaf(b0, ws0, acc[j][0]), 0.f);
            float r1 = fmaxf(fmaf(b1, ws0, acc[j][1]), 0.f);
            if (write_xh) xout[node0 * 32 + (o >> 1)] = __floats2half2_rn(r0, r1);
            float2 h = *(float2*)&hidden[node0 * 64 + o];
            h.x = fmaf(r0, t, h.x);
            h.y = fmaf(r1, t, h.y);
            *(float2*)&hidden[node0 * 64 + o] = h;
        }
        if (node1 < N) {
            float r2 = fmaxf(fmaf(b0, ws1, acc[j][2]), 0.f);
            float r3 = fmaxf(fmaf(b1, ws1, acc[j][3]), 0.f);
            if (write_xh) xout[node1 * 32 + (o >> 1)] = __floats2half2_rn(r2, r3);
            float2 h = *(float2*)&hidden[node1 * 64 + o];
            h.x = fmaf(r2, t, h.x);
            h.y = fmaf(r3, t, h.y);
            *(float2*)&hidden[node1 * 64 + o] = h;
        }
    }
}

extern "C" void kernel_launch(void* const* d_in, const int* in_sizes, int n_in,
                              void* d_out, int out_size) {
    const float* x    = (const float*)d_in[0];
    const float* w    = (const float*)d_in[1];
    const float* W    = (const float*)d_in[2];
    const float* b    = (const float*)d_in[3];
    const float* temp = (const float*)d_in[4];
    const int*   src  = (const int*)d_in[5];
    const int*   dst  = (const int*)d_in[6];
    float* hidden = (float*)d_out;

    int nd = in_sizes[0];          // N * D
    int N  = nd / D;
    int E  = in_sizes[1];
    int L  = in_sizes[3] / D;
    int nd2 = nd / 2;

    k_zero<<<(N + 255) / 256, 256>>>(N);
    int e4 = (E + 3) / 4;
    int mx = (e4 > nd2) ? e4 : nd2;
    k_initcnt<<<(mx + 255) / 256, 256>>>(x, temp, dst, hidden, nd2, E);
    int nb = (N + SCAN_BLK - 1) / SCAN_BLK;
    k_scan1<<<nb, SCAN_BLK>>>(N, nb);
    k_fill<<<(e4 + 255) / 256, 256>>>(src, dst, w, E);

    int layer_blocks = (N + 63) / 64;
    for (int i = 0; i < L; i++) {
        int write_xh = (i + 1 < L) ? 1 : 0;
        if (i == 0) k_layer<1><<<layer_blocks, 256>>>(W, b, temp, 0, write_xh, hidden, N);
        else        k_layer<0><<<layer_blocks, 256>>>(W + i * D * D, b + i * D, temp, i,
                                                      write_xh, hidden, N);
    }
}

// round 12
// speedup vs baseline: 1.2669x; 1.1235x over previous
#include <cuda_runtime.h>
#include <cuda_fp16.h>
#include <cstdint>

#define D 64
#define NODES_CAP 50000
#define EDGES_CAP 1600000
#define SCAN_BLK 1024

// ---------------- scratch (static device globals; no allocation) ----------------
__device__ int   g_counts[NODES_CAP];
__device__ int   g_roff[NODES_CAP];      // partial prefix; after fill: +bsum = final roff[n+1]
__device__ int   g_bsum[64];
__device__ int   g_scan_done;
__device__ float g_wsum[NODES_CAP];
__device__ int2  g_edge[EDGES_CAP];      // (src, float_as_int(w))
// double-buffered fp16 feature rows: layer i reads g_xh[i&1], writes g_xh[(i+1)&1]
__device__ __align__(128) __half2 g_xh[2][NODES_CAP * 32];

// ---------------- zero counters ----------------
__global__ void k_zero(int n_nodes) {
    int i = blockIdx.x * blockDim.x + threadIdx.x;
    if (i < n_nodes) g_counts[i] = 0;
    if (i == 0) g_scan_done = 0;
}

// ---------------- fused init (fp16 convert + hidden=x*t0) + degree histogram ----------------
__global__ void k_initcnt(const float* __restrict__ x, const float* __restrict__ temp,
                          const int* __restrict__ dst,
                          float* __restrict__ hidden, int nd2, int E) {
    int i = blockIdx.x * blockDim.x + threadIdx.x;
    if (i < nd2) {
        float t0 = __ldg(&temp[0]);
        float2 v = ((const float2*)x)[i];
        g_xh[0][i] = __floats2half2_rn(v.x, v.y);
        ((float2*)hidden)[i] = make_float2(v.x * t0, v.y * t0);
    }
    int e4 = i * 4;
    if (e4 + 4 <= E) {
        int4 d4 = __ldg((const int4*)&dst[e4]);
        atomicAdd(&g_counts[d4.x], 1);
        atomicAdd(&g_counts[d4.y], 1);
        atomicAdd(&g_counts[d4.z], 1);
        atomicAdd(&g_counts[d4.w], 1);
    } else {
        for (int e = e4; e < E; e++) atomicAdd(&g_counts[__ldg(&dst[e])], 1);
    }
}

// ---------------- scan1 + folded block-sum scan (last-block pattern) ----------------
__global__ void k_scan1(int N, int nb) {
    __shared__ int s[SCAN_BLK];
    __shared__ int is_last;
    int tid = threadIdx.x;
    int i = blockIdx.x * SCAN_BLK + tid;
    int v = (i < N) ? g_counts[i] : 0;
    s[tid] = v;
    __syncthreads();
    for (int off = 1; off < SCAN_BLK; off <<= 1) {
        int t = (tid >= off) ? s[tid - off] : 0;
        __syncthreads();
        s[tid] += t;
        __syncthreads();
    }
    if (i < N) g_roff[i] = s[tid] - v;          // block-local exclusive prefix
    if (tid == SCAN_BLK - 1) g_bsum[blockIdx.x] = s[tid];
    __threadfence();
    if (tid == 0) is_last = (atomicAdd(&g_scan_done, 1) == nb - 1);
    __syncthreads();
    if (is_last && tid < 32) {
        int lane = tid;
        int v0 = (lane < nb) ? g_bsum[lane] : 0;
        int v1 = (lane + 32 < nb) ? g_bsum[lane + 32] : 0;
        int s0 = v0;
        #pragma unroll
        for (int off = 1; off < 32; off <<= 1) {
            int t = __shfl_up_sync(0xffffffffu, s0, off);
            if (lane >= off) s0 += t;
        }
        int tot0 = __shfl_sync(0xffffffffu, s0, 31);
        int s1 = v1;
        #pragma unroll
        for (int off = 1; off < 32; off <<= 1) {
            int t = __shfl_up_sync(0xffffffffu, s1, off);
            if (lane >= off) s1 += t;
        }
        if (lane < nb) g_bsum[lane] = s0 - v0;                  // exclusive
        if (lane + 32 < nb) g_bsum[lane + 32] = tot0 + s1 - v1;
    }
}

// ---------------- CSR fill: bump partial roff directly, add block offset at use ----------------
// After this kernel: g_roff[n] + g_bsum[n>>10] == final_roff[n+1]
__global__ void k_fill(const int* __restrict__ src, const int* __restrict__ dst,
                       const float* __restrict__ w, int E) {
    int i = blockIdx.x * blockDim.x + threadIdx.x;
    int e4 = i * 4;
    if (e4 + 4 <= E) {
        int4   s4 = __ldg((const int4*)&src[e4]);
        int4   d4 = __ldg((const int4*)&dst[e4]);
        float4 w4 = __ldg((const float4*)&w[e4]);
        int p0 = atomicAdd(&g_roff[d4.x], 1) + g_bsum[d4.x >> 10];
        int p1 = atomicAdd(&g_roff[d4.y], 1) + g_bsum[d4.y >> 10];
        int p2 = atomicAdd(&g_roff[d4.z], 1) + g_bsum[d4.z >> 10];
        int p3 = atomicAdd(&g_roff[d4.w], 1) + g_bsum[d4.w >> 10];
        g_edge[p0] = make_int2(s4.x, __float_as_int(w4.x));
        g_edge[p1] = make_int2(s4.y, __float_as_int(w4.y));
        g_edge[p2] = make_int2(s4.z, __float_as_int(w4.z));
        g_edge[p3] = make_int2(s4.w, __float_as_int(w4.w));
    } else {
        for (int e = e4; e < E; e++) {
            int d = __ldg(&dst[e]);
            int p = atomicAdd(&g_roff[d], 1) + g_bsum[d >> 10];
            g_edge[p] = make_int2(__ldg(&src[e]), __float_as_int(__ldg(&w[e])));
        }
    }
}

// ---------------- fused per-layer kernel: SpMM (into smem) + tf32 MMA + epilogue ----------------
// Phase 1: each QUARTER-WARP owns one node (8 lanes x 16B = one 128B row line per gather);
// a warp walks its 8 nodes as 2 quads -> four independent edge streams in flight.
// Warp stays converged: loop to the quad max with zero-weight padding.
__device__ __forceinline__ uint32_t f2tf32(float f) {
    uint32_t r;
    asm("cvt.rna.tf32.f32 %0, %1;" : "=r"(r) : "f"(f));
    return r;
}

template <int STORE_WSUM>
__global__ void k_layer(const float* __restrict__ Wl, const float* __restrict__ bl,
                        const float* __restrict__ temp, int li, int write_xh,
                        float* __restrict__ hidden, int N) {
    __shared__ uint32_t As[64][68];   // As[node][d], tf32 bits
    __shared__ uint32_t Ws[64][68];   // Ws[o][d], tf32 bits
    int tid = threadIdx.x;
    int wid = tid >> 5, lane = tid & 31;
    int bn = blockIdx.x * 64;
    float t = __ldg(&temp[li + 1]);
    const __half2* __restrict__ xin = g_xh[li & 1];
    __half2* __restrict__ xout = g_xh[(li + 1) & 1];

    for (int idx = tid; idx < 4096; idx += 256) {
        Ws[idx >> 6][idx & 63] = f2tf32(__ldg(&Wl[idx]));   // idx == o*64+d
    }

    int quarter = lane >> 3;   // which node of the quad (0..3)
    int ql      = lane & 7;    // lane within quarter-warp; features 8*ql..8*ql+7

    // ---- Phase 1: SpMM, quarter-warp per node, 2 node-quads per warp ----
    #pragma unroll 1
    for (int k = 0; k < 2; k++) {
        int nloc = wid * 8 + k * 4 + quarter;
        int node = bn + nloc;
        float acc[8] = {};
        float ws = 0.f;
        int beg = 0, end = 0;
        if (node < N) {
            beg = (node == 0) ? 0 : (__ldg(&g_roff[node - 1]) + g_bsum[(node - 1) >> 10]);
            end = __ldg(&g_roff[node]) + g_bsum[node >> 10];
        }
        int cnt = end - beg;
        int m1 = max(cnt, __shfl_xor_sync(0xffffffffu, cnt, 8));
        int mxcnt = max(m1, __shfl_xor_sync(0xffffffffu, m1, 16));
        int e = beg;
        for (int it = 0; it < mxcnt; it += 8, e += 8) {
            int2 ed[8];
            uint4 v[8];
            #pragma unroll
            for (int j = 0; j < 8; j++)
                ed[j] = (e + j < end) ? __ldg(&g_edge[e + j]) : make_int2(0, 0);
            #pragma unroll
            for (int j = 0; j < 8; j++)
                v[j] = __ldg((const uint4*)(xin + ed[j].x * 32) + ql);
            #pragma unroll
            for (int j = 0; j < 8; j++) {
                float wt = __int_as_float(ed[j].y);     // 0.0f for padding
                if (STORE_WSUM) ws += wt;
                float2 f0 = __half22float2(*(__half2*)&v[j].x);
                float2 f1 = __half22float2(*(__half2*)&v[j].y);
                float2 f2 = __half22float2(*(__half2*)&v[j].z);
                float2 f3 = __half22float2(*(__half2*)&v[j].w);
                acc[0] = fmaf(f0.x, wt, acc[0]);
                acc[1] = fmaf(f0.y, wt, acc[1]);
                acc[2] = fmaf(f1.x, wt, acc[2]);
                acc[3] = fmaf(f1.y, wt, acc[3]);
                acc[4] = fmaf(f2.x, wt, acc[4]);
                acc[5] = fmaf(f2.y, wt, acc[5]);
                acc[6] = fmaf(f3.x, wt, acc[6]);
                acc[7] = fmaf(f3.y, wt, acc[7]);
            }
        }
        if (STORE_WSUM && ql == 0 && node < N) g_wsum[node] = ws;
        #pragma unroll
        for (int c = 0; c < 8; c++)
            As[nloc][8 * ql + c] = f2tf32(acc[c]);
    }
    __syncthreads();

    // ---- Phase 2: tf32 MMA, m16n32 per warp ----
    int g = lane >> 2, tg = lane & 3;
    int m0 = (wid & 3) * 16;
    int n0 = (wid >> 2) * 32;

    float acc[4][4] = {};
    #pragma unroll
    for (int k0 = 0; k0 < 64; k0 += 8) {
        uint32_t a0 = As[m0 + g][k0 + tg];
        uint32_t a1 = As[m0 + g + 8][k0 + tg];
        uint32_t a2 = As[m0 + g][k0 + tg + 4];
        uint32_t a3 = As[m0 + g + 8][k0 + tg + 4];
        #pragma unroll
        for (int j = 0; j < 4; j++) {
            uint32_t b0 = Ws[n0 + j * 8 + g][k0 + tg];
            uint32_t b1 = Ws[n0 + j * 8 + g][k0 + tg + 4];
            asm volatile(
                "mma.sync.aligned.m16n8k8.row.col.f32.tf32.tf32.f32 "
                "{%0,%1,%2,%3}, {%4,%5,%6,%7}, {%8,%9}, {%0,%1,%2,%3};"
                : "+f"(acc[j][0]), "+f"(acc[j][1]), "+f"(acc[j][2]), "+f"(acc[j][3])
                : "r"(a0), "r"(a1), "r"(a2), "r"(a3), "r"(b0), "r"(b1));
        }
    }

    // epilogue: thread holds rows (m0+g, m0+g+8), cols (2tg, 2tg+1) per n8-tile
    int node0 = bn + m0 + g;
    int node1 = node0 + 8;
    float ws0 = (node0 < N) ? g_wsum[node0] : 0.f;
    float ws1 = (node1 < N) ? g_wsum[node1] : 0.f;
    #pragma unroll
    for (int j = 0; j < 4; j++) {
        int o = n0 + j * 8 + 2 * tg;
        float b0 = __ldg(&bl[o]), b1 = __ldg(&bl[o + 1]);
        if (node0 < N) {
            float r0 = fmaxf(fmaf(b0, ws0, acc[j][0]), 0.f);
            float r1 = fmaxf(fmaf(b1, ws0, acc[j][1]), 0.f);
            if (write_xh) xout[node0 * 32 + (o >> 1)] = __floats2half2_rn(r0, r1);
            float2 h = *(float2*)&hidden[node0 * 64 + o];
            h.x = fmaf(r0, t, h.x);
            h.y = fmaf(r1, t, h.y);
            *(float2*)&hidden[node0 * 64 + o] = h;
        }
        if (node1 < N) {
            float r2 = fmaxf(fmaf(b0, ws1, acc[j][2]), 0.f);
            float r3 = fmaxf(fmaf(b1, ws1, acc[j][3]), 0.f);
            if (write_xh) xout[node1 * 32 + (o >> 1)] = __floats2half2_rn(r2, r3);
            float2 h = *(float2*)&hidden[node1 * 64 + o];
            h.x = fmaf(r2, t, h.x);
            h.y = fmaf(r3, t, h.y);
            *(float2*)&hidden[node1 * 64 + o] = h;
        }
    }
}

extern "C" void kernel_launch(void* const* d_in, const int* in_sizes, int n_in,
                              void* d_out, int out_size) {
    const float* x    = (const float*)d_in[0];
    const float* w    = (const float*)d_in[1];
    const float* W    = (const float*)d_in[2];
    const float* b    = (const float*)d_in[3];
    const float* temp = (const float*)d_in[4];
    const int*   src  = (const int*)d_in[5];
    const int*   dst  = (const int*)d_in[6];
    float* hidden = (float*)d_out;

    int nd = in_sizes[0];          // N * D
    int N  = nd / D;
    int E  = in_sizes[1];
    int L  = in_sizes[3] / D;
    int nd2 = nd / 2;

    k_zero<<<(N + 255) / 256, 256>>>(N);
    int e4 = (E + 3) / 4;
    int mx = (e4 > nd2) ? e4 : nd2;
    k_initcnt<<<(mx + 255) / 256, 256>>>(x, temp, dst, hidden, nd2, E);
    int nb = (N + SCAN_BLK - 1) / SCAN_BLK;
    k_scan1<<<nb, SCAN_BLK>>>(N, nb);
    k_fill<<<(e4 + 255) / 256, 256>>>(src, dst, w, E);

    int layer_blocks = (N + 63) / 64;
    for (int i = 0; i < L; i++) {
        int write_xh = (i + 1 < L) ? 1 : 0;
        if (i == 0) k_layer<1><<<layer_blocks, 256>>>(W, b, temp, 0, write_xh, hidden, N);
        else        k_layer<0><<<layer_blocks, 256>>>(W + i * D * D, b + i * D, temp, i,
                                                      write_xh, hidden, N);
    }
}